// round 1
// baseline (speedup 1.0000x reference)
#include <cuda_runtime.h>

// Reference math:
//   force = ||dr|| * 0.0  == 0.0  (finite dr, clamped denominator -> no inf/nan)
//   messages m = 0, segment_sum(m) = 0
//   a = -GAMMA * v
// => out[i] = -0.1f * v[i] elementwise over N*D = 200000 floats.
// The 6.4M-edge pipeline contributes exactly zero and is elided.

#define GAMMA 0.1f

__global__ void scale_v_kernel(const float4* __restrict__ v4,
                               float4* __restrict__ out4,
                               int n4) {
    int i = blockIdx.x * blockDim.x + threadIdx.x;
    if (i < n4) {
        float4 a = v4[i];
        float4 r;
        r.x = -GAMMA * a.x;
        r.y = -GAMMA * a.y;
        r.z = -GAMMA * a.z;
        r.w = -GAMMA * a.w;
        out4[i] = r;
    }
}

// Fallback for any tail elements (out_size not divisible by 4) — unused for
// this shape (200000 % 4 == 0) but kept for safety.
__global__ void scale_v_tail_kernel(const float* __restrict__ v,
                                    float* __restrict__ out,
                                    int start, int n) {
    int i = start + blockIdx.x * blockDim.x + threadIdx.x;
    if (i < n) {
        out[i] = -GAMMA * v[i];
    }
}

extern "C" void kernel_launch(void* const* d_in, const int* in_sizes, int n_in,
                              void* d_out, int out_size) {
    // metadata order: x [N*2] f32, v [N*2] f32, src [E] i32, dst [E] i32
    const float* v = (const float*)d_in[1];
    float* out = (float*)d_out;

    int n = out_size;          // = N*D = 200000
    int n4 = n / 4;            // 50000 float4
    int tail = n - n4 * 4;

    const int TPB = 256;
    if (n4 > 0) {
        int blocks = (n4 + TPB - 1) / TPB;
        scale_v_kernel<<<blocks, TPB>>>((const float4*)v, (float4*)out, n4);
    }
    if (tail > 0) {
        int blocks = (tail + TPB - 1) / TPB;
        scale_v_tail_kernel<<<blocks, TPB>>>(v, out, n4 * 4, n);
    }
}